// round 13
// baseline (speedup 1.0000x reference)
#include <cuda_runtime.h>
#include <cuda_fp16.h>
#include <cstdint>

#define BATCH 8
#define CH    512
#define NPIX  1024
#define HEADS 8
#define HD    64
#define EPSBN 1e-5f

// ---------------- static scratch (no allocs allowed) ----------------
__device__ __half g_xs_t [BATCH * NPIX * CH];   // spiked x, transposed [b][n][c]
__device__ __half g_q    [BATCH * CH * NPIX];   // [b][c][n]
__device__ __half g_k    [BATCH * CH * NPIX];
__device__ __half g_v    [BATCH * CH * NPIX];
__device__ __half g_os_t [BATCH * NPIX * CH];   // spiked attn out, [b][n][c]
__device__ __half g_Msp  [BATCH * HEADS * 2 * HD * HD];  // [bh][hi/lo][d'][d]  (M^T split)
__device__ __half g_wsplit[4 * CH * (2 * CH)];  // per weight: [o][c<512]=hi, [o][512+c]=lo
__device__ float  g_bns[4 * CH];
__device__ float  g_bnb[4 * CH];

__device__ __forceinline__ float spikef(float x) {
    x = fminf(fmaxf(x, 0.0f), 4.0f);
    return rintf(x) * 0.25f;           // round-half-even == jnp.round
}

// ---------------- PTX helpers (baseline sm_80+ features only) ----------------
__device__ __forceinline__ uint32_t smem_u32(const void* p) {
    uint32_t a;
    asm("{ .reg .u64 t; cvta.to.shared.u64 t, %1; cvt.u32.u64 %0, t; }" : "=r"(a) : "l"(p));
    return a;
}
#define CP_ASYNC16(dst, src) \
    asm volatile("cp.async.cg.shared.global [%0], [%1], 16;" :: "r"(dst), "l"(src))
#define CP_COMMIT()  asm volatile("cp.async.commit_group;" ::: "memory")
#define CP_WAIT1()   asm volatile("cp.async.wait_group 1;" ::: "memory")
#define CP_WAIT0()   asm volatile("cp.async.wait_group 0;" ::: "memory")

__device__ __forceinline__ void ldsm_x4(uint32_t& r0, uint32_t& r1, uint32_t& r2, uint32_t& r3,
                                        uint32_t addr) {
    asm volatile("ldmatrix.sync.aligned.m8n8.x4.shared.b16 {%0,%1,%2,%3}, [%4];"
                 : "=r"(r0), "=r"(r1), "=r"(r2), "=r"(r3) : "r"(addr));
}
__device__ __forceinline__ void ldsm_x4_t(uint32_t& r0, uint32_t& r1, uint32_t& r2, uint32_t& r3,
                                          uint32_t addr) {
    asm volatile("ldmatrix.sync.aligned.m8n8.x4.trans.shared.b16 {%0,%1,%2,%3}, [%4];"
                 : "=r"(r0), "=r"(r1), "=r"(r2), "=r"(r3) : "r"(addr));
}
__device__ __forceinline__ void mma16816(float* d, const uint32_t* a, const uint32_t* b) {
    asm volatile(
        "mma.sync.aligned.m16n8k16.row.col.f32.f16.f16.f32 "
        "{%0,%1,%2,%3},{%4,%5,%6,%7},{%8,%9},{%0,%1,%2,%3};"
        : "+f"(d[0]), "+f"(d[1]), "+f"(d[2]), "+f"(d[3])
        : "r"(a[0]), "r"(a[1]), "r"(a[2]), "r"(a[3]), "r"(b[0]), "r"(b[1]));
}
#define SW128(off) ((off) ^ (((off) >> 3) & 0x70))

// ---------------------------------------------------------------------------
// K0: fused preprocessing: wsplit (bid<4096) | spike_t (4096..8191) | bn_prep
// ---------------------------------------------------------------------------
__global__ void preproc_kernel(
    const float* __restrict__ x,
    const float* __restrict__ w0, const float* __restrict__ w1,
    const float* __restrict__ w2, const float* __restrict__ w3,
    const float* __restrict__ qg, const float* __restrict__ qb,
    const float* __restrict__ qm, const float* __restrict__ qv,
    const float* __restrict__ kg, const float* __restrict__ kb,
    const float* __restrict__ km, const float* __restrict__ kv,
    const float* __restrict__ vg, const float* __restrict__ vb,
    const float* __restrict__ vm, const float* __restrict__ vv,
    const float* __restrict__ pg, const float* __restrict__ pb,
    const float* __restrict__ pm, const float* __restrict__ pv)
{
    __shared__ float tile[32][33];
    const int bid = blockIdx.x;
    const int tid = threadIdx.x;

    if (bid < 4096) {
        const float* W[4] = {w0, w1, w2, w3};
        int wi = bid >> 10;
        int idx = (bid & 1023) * 256 + tid;
        int o = idx >> 9, c = idx & 511;
        float w = W[wi][o * 512 + c];
        __half h1 = __float2half_rn(w);
        __half h2 = __float2half_rn(w - __half2float(h1));
        __half* dst = g_wsplit + (size_t)(wi * 512 + o) * 1024;
        dst[c]       = h1;
        dst[512 + c] = h2;
    } else if (bid < 8192) {
        int sid = bid - 4096;
        int n0 = (sid & 31) * 32, c0 = ((sid >> 5) & 15) * 32, b = sid >> 9;
        int tx = tid & 31, ty = tid >> 5;
        const float* xb = x + (size_t)b * CH * NPIX;
#pragma unroll
        for (int i = 0; i < 4; i++)
            tile[ty + i * 8][tx] = spikef(xb[(size_t)(c0 + ty + i * 8) * NPIX + n0 + tx]);
        __syncthreads();
        __half* ob = g_xs_t + (size_t)b * NPIX * CH;
#pragma unroll
        for (int i = 0; i < 4; i++)
            ob[(size_t)(n0 + ty + i * 8) * CH + c0 + tx] = __float2half_rn(tile[tx][ty + i * 8]);
    } else {
        int idx = (bid - 8192) * 256 + tid;      // 0..2047
        int wi = idx >> 9, c = idx & 511;
        const float* G[4] = {qg, kg, vg, pg};
        const float* Bb[4] = {qb, kb, vb, pb};
        const float* Mm[4] = {qm, km, vm, pm};
        const float* Vv[4] = {qv, kv, vv, pv};
        float s = G[wi][c] / sqrtf(Vv[wi][c] + EPSBN);
        g_bns[idx] = s;
        g_bnb[idx] = Bb[wi][c] - Mm[wi][c] * s;
    }
}

// ---------------------------------------------------------------------------
// K2: mma.sync conv_bn GEMM — R7 config (best measured). Tile M=128, N=64,
// BK=64, 3-stage cp.async, 8 warps (4m x 2n), warp tile 32x32, 3 CTAs/SM.
// ---------------------------------------------------------------------------
template <bool SPIKE, bool FUSED, typename OutT>
__global__ __launch_bounds__(256, 3)
void conv_mma_kernel(const __half* __restrict__ Wsp,   // [M][1024]
                     const __half* __restrict__ Bact,  // [B][1024][512]
                     const float* __restrict__ bns,
                     const float* __restrict__ bnb,
                     OutT* __restrict__ Yq, OutT* __restrict__ Yk, OutT* __restrict__ Yv)
{
    extern __shared__ char dsm[];
    const int tid  = threadIdx.x;
    const int wid  = tid >> 5, lane = tid & 31;
    const int b      = blockIdx.z;
    const int tile_n = blockIdx.x * 64;
    const int tile_m = blockIdx.y * 128;
    const int warp_m = (wid & 3) * 32;
    const int warp_n = (wid >> 2) * 32;

    OutT* Yb;
    if (FUSED) {
        const int wi = tile_m >> 9;
        Yb = (wi == 0) ? Yq : ((wi == 1) ? Yk : Yv);
    } else {
        Yb = Yq;
    }

    uint32_t base = (smem_u32(dsm) + 1023) & ~1023u;
    uint32_t sA[3], sB[3];
#pragma unroll
    for (int s = 0; s < 3; s++) { sA[s] = base + s * 24576; sB[s] = sA[s] + 16384; }

    const __half* Bb   = Bact + (size_t)b * NPIX * CH;
    const __half* Arow = Wsp + (size_t)(tile_m + (tid >> 1)) * 1024 + (tid & 1) * 32;
    const __half* Brow = Bb  + (size_t)(tile_n + (tid >> 2)) * 512  + (tid & 3) * 16;

    uint32_t stgA[4], stgB[2];
#pragma unroll
    for (int i = 0; i < 4; i++)
        stgA[i] = SW128((uint32_t)(tid >> 1) * 128 + ((tid & 1) * 4 + i) * 16);
#pragma unroll
    for (int i = 0; i < 2; i++)
        stgB[i] = SW128((uint32_t)(tid >> 2) * 128 + ((tid & 3) * 2 + i) * 16);

    const uint32_t aoff = (uint32_t)(warp_m + (lane & 15)) * 128 + (lane >> 4) * 16;
    const uint32_t boff = (uint32_t)(warp_n + ((lane >> 4) & 1) * 8 + (lane & 7)) * 128
                        + ((lane >> 3) & 1) * 16;

    float acc[2][4][4];
#pragma unroll
    for (int mt = 0; mt < 2; mt++)
#pragma unroll
        for (int nt = 0; nt < 4; nt++)
#pragma unroll
            for (int e = 0; e < 4; e++) acc[mt][nt][e] = 0.0f;

#pragma unroll
    for (int st = 0; st < 2; st++) {
#pragma unroll
        for (int i = 0; i < 4; i++) CP_ASYNC16(sA[st] + stgA[i], Arow + st * 64 + i * 8);
#pragma unroll
        for (int i = 0; i < 2; i++) CP_ASYNC16(sB[st] + stgB[i], Brow + st * 64 + i * 8);
        CP_COMMIT();
    }
    CP_WAIT1();
    __syncthreads();

#pragma unroll 1
    for (int ch = 0; ch < 16; ch++) {
        if (ch < 14) {
            const int st = (ch + 2) % 3;
            const __half* An = Arow + (size_t)(ch + 2) * 64;
            const __half* Bn = Brow + (size_t)((ch + 2) & 7) * 64;
#pragma unroll
            for (int i = 0; i < 4; i++) CP_ASYNC16(sA[st] + stgA[i], An + i * 8);
#pragma unroll
            for (int i = 0; i < 2; i++) CP_ASYNC16(sB[st] + stgB[i], Bn + i * 8);
            CP_COMMIT();
        }

        const uint32_t A0 = sA[ch % 3], B0 = sB[ch % 3];
#pragma unroll
        for (int s = 0; s < 4; s++) {
            uint32_t af[2][4], bf[2][4];
#pragma unroll
            for (int mt = 0; mt < 2; mt++)
                ldsm_x4(af[mt][0], af[mt][1], af[mt][2], af[mt][3],
                        A0 + SW128(aoff + mt * 2048 + s * 32));
#pragma unroll
            for (int p = 0; p < 2; p++)
                ldsm_x4(bf[p][0], bf[p][1], bf[p][2], bf[p][3],
                        B0 + SW128(boff + p * 2048 + s * 32));
#pragma unroll
            for (int mt = 0; mt < 2; mt++)
#pragma unroll
                for (int nt = 0; nt < 4; nt++)
                    mma16816(acc[mt][nt], af[mt], &bf[nt >> 1][(nt & 1) * 2]);
        }

        if (ch < 15) {
            if (ch < 14) { CP_WAIT1(); } else { CP_WAIT0(); }
            __syncthreads();
        }
    }

    const int r0 = lane >> 2;
    const int c0 = (lane & 3) * 2;
#pragma unroll
    for (int mt = 0; mt < 2; mt++) {
#pragma unroll
        for (int half = 0; half < 2; half++) {
            const int o = tile_m + warp_m + mt * 16 + r0 + half * 8;
            const float s    = bns[o];
            const float beta = bnb[o];
            OutT* yrow = Yb + ((size_t)b * 512 + (o & 511)) * 1024;
#pragma unroll
            for (int nt = 0; nt < 4; nt++) {
                const int n = tile_n + warp_n + nt * 8 + c0;
                float y0 = fmaf(acc[mt][nt][half * 2 + 0], s, beta);
                float y1 = fmaf(acc[mt][nt][half * 2 + 1], s, beta);
                if (SPIKE) {
                    __half2 hh = __floats2half2_rn(spikef(y0), spikef(y1));
                    *reinterpret_cast<__half2*>((__half*)yrow + n) = hh;
                } else {
                    *reinterpret_cast<float2*>((float*)yrow + n) = make_float2(y0, y1);
                }
            }
        }
    }
}

// ---------------------------------------------------------------------------
// K3: ktv via mma.sync, ONE block per bh, 256 threads (8 warps: 2 d x 4 d',
// warp tile 32x16). K=1024 in-block, exact fp32 sums. Epilogue writes M^T
// split hi/lo fp16 (exact: M multiples of 1/16, |M|<=1024 -> <=14 sig bits).
// ---------------------------------------------------------------------------
__global__ __launch_bounds__(256)
void ktv_mma_kernel() {
    __shared__ char sm[2 * 16384];
    const int tid = threadIdx.x;
    const int wid = tid >> 5, lane = tid & 31;
    const int bh = blockIdx.x;
    const int b = bh >> 3, h = bh & 7;
    const int warp_m = (wid & 1) * 32;      // d rows
    const int warp_n = (wid >> 1) * 16;     // d' rows

    uint32_t base = smem_u32(sm);
    uint32_t sK[2] = {base,         base + 8192};
    uint32_t sV[2] = {base + 16384, base + 24576};

    const __half* Kb = g_k + (size_t)b * CH * NPIX + (size_t)h * HD * NPIX;
    const __half* Vb = g_v + (size_t)b * CH * NPIX + (size_t)h * HD * NPIX;

    const int srow = tid >> 2, scb = (tid & 3) * 2;
    const __half* Krow = Kb + (size_t)srow * NPIX + scb * 8;
    const __half* Vrow = Vb + (size_t)srow * NPIX + scb * 8;
    uint32_t stg[2];
#pragma unroll
    for (int j = 0; j < 2; j++)
        stg[j] = SW128((uint32_t)srow * 128 + (scb + j) * 16);

    const uint32_t aoff = (uint32_t)(warp_m + (lane & 15)) * 128 + (lane >> 4) * 16;
    const uint32_t boff = (uint32_t)(warp_n + ((lane >> 4) & 1) * 8 + (lane & 7)) * 128
                        + ((lane >> 3) & 1) * 16;

    float acc[2][2][4];
#pragma unroll
    for (int mt = 0; mt < 2; mt++)
#pragma unroll
        for (int nt = 0; nt < 2; nt++)
#pragma unroll
            for (int e = 0; e < 4; e++) acc[mt][nt][e] = 0.0f;

#pragma unroll
    for (int j = 0; j < 2; j++) {
        CP_ASYNC16(sK[0] + stg[j], Krow + j * 8);
        CP_ASYNC16(sV[0] + stg[j], Vrow + j * 8);
    }
    CP_COMMIT();

#pragma unroll 1
    for (int ch = 0; ch < 16; ch++) {
        __syncthreads();
        if (ch < 15) {
            const int st = (ch + 1) & 1;
#pragma unroll
            for (int j = 0; j < 2; j++) {
                CP_ASYNC16(sK[st] + stg[j], Krow + (ch + 1) * 64 + j * 8);
                CP_ASYNC16(sV[st] + stg[j], Vrow + (ch + 1) * 64 + j * 8);
            }
            CP_COMMIT();
            CP_WAIT1();
        } else {
            CP_WAIT0();
        }
        __syncthreads();

        const uint32_t A0 = sK[ch & 1], B0 = sV[ch & 1];
#pragma unroll
        for (int s = 0; s < 4; s++) {
            uint32_t af[2][4], bf[4];
#pragma unroll
            for (int mt = 0; mt < 2; mt++)
                ldsm_x4(af[mt][0], af[mt][1], af[mt][2], af[mt][3],
                        A0 + SW128(aoff + mt * 2048 + s * 32));
            ldsm_x4(bf[0], bf[1], bf[2], bf[3], B0 + SW128(boff + s * 32));
#pragma unroll
            for (int mt = 0; mt < 2; mt++)
#pragma unroll
                for (int nt = 0; nt < 2; nt++)
                    mma16816(acc[mt][nt], af[mt], &bf[nt * 2]);
        }
    }

    __half* Mp = g_Msp + (size_t)bh * 8192;
    const int r0 = lane >> 2, c0 = (lane & 3) * 2;
#pragma unroll
    for (int mt = 0; mt < 2; mt++)
#pragma unroll
        for (int half = 0; half < 2; half++) {
            const int d = warp_m + mt * 16 + r0 + half * 8;
#pragma unroll
            for (int nt = 0; nt < 2; nt++) {
#pragma unroll
                for (int e = 0; e < 2; e++) {
                    const int dp = warp_n + nt * 8 + c0 + e;
                    float v = acc[mt][nt][half * 2 + e];
                    __half hi = __float2half_rn(v);
                    __half lo = __float2half_rn(v - __half2float(hi));
                    Mp[dp * 64 + d]        = hi;
                    Mp[4096 + dp * 64 + d] = lo;
                }
            }
        }
}

// ---------------------------------------------------------------------------
// K4: qm persistent-per-bh. grid 64 CTAs, 256 thr (8 warps: 2 d' x 4 n32).
// Loads Msp ONCE, loops 8 n-tiles with double-buffered cp.async q staging.
// D[d'][n] = sum_d (Mhi+Mlo)^T[d'][d] * q[d][n]; os_t = fp16(spike(0.25*D)).
// smem layout (dynamic): [0,16K) Msp | [16K,32K) qbuf0 | [32K,48K) qbuf1 |
//                        [48K,48K+16.5K) ds epilogue scratch
// ---------------------------------------------------------------------------
static constexpr int QM_SMEM = 49152 + 64 * 132 * 2;   // 66048

__global__ __launch_bounds__(256)
void qm_tc_kernel() {
    extern __shared__ __align__(16) char qsm[];
    const int tid = threadIdx.x;
    const int wid = tid >> 5, lane = tid & 31;
    const int bh = blockIdx.x;
    const int b = bh >> 3, h = bh & 7;
    const uint32_t base = smem_u32(qsm);
    const uint32_t QB[2] = {base + 16384, base + 32768};
    __half* ds = (__half*)(qsm + 49152);

    // stage Msp once: 2 planes x 64 rows(d') x 128B, SW128 within plane
    const int4* gmsp = (const int4*)(g_Msp + (size_t)bh * 8192);
#pragma unroll
    for (int l = 0; l < 4; l++) {
        int i = tid + l * 256;                 // 0..1023 16B chunks
        int j = i & 511;
        uint32_t off = (uint32_t)(i >> 9) * 8192 + SW128((uint32_t)(j >> 3) * 128 + (j & 7) * 16);
        *(int4*)(qsm + off) = gmsp[i];
    }

    // q tile staging helper geometry (per thread: 4 x 16B chunks per tile)
    const __half* Qb = g_q + (size_t)b * CH * NPIX + (size_t)h * HD * NPIX;

    // prologue: ntile 0 -> buf 0
#pragma unroll
    for (int l = 0; l < 4; l++) {
        int i = tid + l * 256;
        int s = i >> 9, j = i & 511;
        int d = j >> 3, c = j & 7;
        uint32_t off = QB[0] + (uint32_t)s * 8192 + SW128((uint32_t)d * 128 + c * 16);
        CP_ASYNC16(off, Qb + (size_t)d * NPIX + s * 64 + c * 8);
    }
    CP_COMMIT();

    const int warp_m = (wid & 1) * 32;                      // d' range
    const int wn = wid >> 1;                                // 0..3, n base = wn*32
    const int r0 = lane >> 2, c0 = (lane & 3) * 2;

#pragma unroll 1
    for (int nt = 0; nt < 8; nt++) {
        // prefetch next tile into the other buffer
        if (nt < 7) {
#pragma unroll
            for (int l = 0; l < 4; l++) {
                int i = tid + l * 256;
                int s = i >> 9, j = i & 511;
                int d = j >> 3, c = j & 7;
                uint32_t off = QB[(nt + 1) & 1] + (uint32_t)s * 8192
                             + SW128((uint32_t)d * 128 + c * 16);
                CP_ASYNC16(off, Qb + (size_t)d * NPIX + (nt + 1) * 128 + s * 64 + c * 8);
            }
            CP_COMMIT();
            CP_WAIT1();        // tile nt's group has drained
        } else {
            CP_WAIT0();
        }
        __syncthreads();       // publish tile nt (and Msp on first iter)

        const uint32_t qsub = QB[nt & 1] + (uint32_t)(wn >> 1) * 8192;
        const uint32_t colb = (uint32_t)(wn & 1) * 64;

        float acc[2][4][4];
#pragma unroll
        for (int mt = 0; mt < 2; mt++)
#pragma unroll
            for (int nn = 0; nn < 4; nn++)
#pragma unroll
                for (int e = 0; e < 4; e++) acc[mt][nn][e] = 0.0f;

#pragma unroll
        for (int plane = 0; plane < 2; plane++) {
            const uint32_t Ab = base + plane * 8192;
#pragma unroll
            for (int s = 0; s < 4; s++) {
                uint32_t af[2][4], bf[2][4];
#pragma unroll
                for (int mt = 0; mt < 2; mt++)
                    ldsm_x4(af[mt][0], af[mt][1], af[mt][2], af[mt][3],
                            Ab + SW128((uint32_t)(warp_m + mt * 16 + (lane & 15)) * 128
                                       + s * 32 + (lane >> 4) * 16));
                const int krow = s * 16 + (lane & 7) + ((lane >> 3) & 1) * 8;
#pragma unroll
                for (int nb = 0; nb < 2; nb++)
                    ldsm_x4_t(bf[nb][0], bf[nb][1], bf[nb][2], bf[nb][3],
                              qsub + SW128((uint32_t)krow * 128 + colb + nb * 32
                                           + (lane >> 4) * 16));
#pragma unroll
                for (int mt = 0; mt < 2; mt++)
#pragma unroll
                    for (int nn = 0; nn < 4; nn++)
                        mma16816(acc[mt][nn], af[mt], &bf[nn >> 1][(nn & 1) * 2]);
            }
        }

        // epilogue: spike(0.25*D) -> ds -> coalesced os_t rows
#pragma unroll
        for (int mt = 0; mt < 2; mt++)
#pragma unroll
            for (int half = 0; half < 2; half++) {
                const int dp = warp_m + mt * 16 + r0 + half * 8;
#pragma unroll
                for (int nn = 0; nn < 4; nn++) {
                    const int nloc = wn * 32 + nn * 8 + c0;
                    float y0 = spikef(acc[mt][nn][half * 2 + 0] * 0.25f);
                    float y1 = spikef(acc[mt][nn][half * 2 + 1] * 0.25f);
                    *reinterpret_cast<__half2*>(ds + dp * 132 + nloc) =
                        __floats2half2_rn(y0, y1);
                }
            }
        __syncthreads();

        if (tid < 128) {
            __half hv[64];
#pragma unroll
            for (int dp = 0; dp < 64; dp++) hv[dp] = ds[dp * 132 + tid];
            __half* Ob = g_os_t + (size_t)b * NPIX * CH
                       + (size_t)(nt * 128 + tid) * CH + h * 64;
#pragma unroll
            for (int i = 0; i < 8; i++)
                *reinterpret_cast<int4*>(Ob + i * 8) = reinterpret_cast<int4*>(hv)[i];
        }
        __syncthreads();       // ds free; qbuf[(nt+2)&1] readers done before next prefetch
    }
}

// ---------------------------------------------------------------------------
// launch
// ---------------------------------------------------------------------------
static constexpr int CONV_SMEM = 3 * 24576 + 1024;   // 74752

extern "C" void kernel_launch(void* const* d_in, const int* in_sizes, int n_in,
                              void* d_out, int out_size) {
    (void)in_sizes; (void)n_in; (void)out_size;
    const float* x  = (const float*)d_in[0];
    const float* qw = (const float*)d_in[1];
    const float* qg = (const float*)d_in[2];
    const float* qb = (const float*)d_in[3];
    const float* qm = (const float*)d_in[4];
    const float* qv = (const float*)d_in[5];
    const float* kw = (const float*)d_in[6];
    const float* kg = (const float*)d_in[7];
    const float* kb = (const float*)d_in[8];
    const float* km = (const float*)d_in[9];
    const float* kv = (const float*)d_in[10];
    const float* vw = (const float*)d_in[11];
    const float* vg = (const float*)d_in[12];
    const float* vb = (const float*)d_in[13];
    const float* vm = (const float*)d_in[14];
    const float* vv = (const float*)d_in[15];
    const float* pw = (const float*)d_in[16];
    const float* pg = (const float*)d_in[17];
    const float* pb = (const float*)d_in[18];
    const float* pm = (const float*)d_in[19];
    const float* pv = (const float*)d_in[20];
    float* out = (float*)d_out;

    __half *xs_t, *q, *k, *v, *os_t, *wsp;
    float *bns, *bnb;
    cudaGetSymbolAddress((void**)&xs_t, g_xs_t);
    cudaGetSymbolAddress((void**)&q,    g_q);
    cudaGetSymbolAddress((void**)&k,    g_k);
    cudaGetSymbolAddress((void**)&v,    g_v);
    cudaGetSymbolAddress((void**)&os_t, g_os_t);
    cudaGetSymbolAddress((void**)&wsp,  g_wsplit);
    cudaGetSymbolAddress((void**)&bns,  g_bns);
    cudaGetSymbolAddress((void**)&bnb,  g_bnb);

    static bool attr_done = false;
    if (!attr_done) {
        cudaFuncSetAttribute(conv_mma_kernel<true,  true,  __half>,
                             cudaFuncAttributeMaxDynamicSharedMemorySize, CONV_SMEM);
        cudaFuncSetAttribute(conv_mma_kernel<false, false, float>,
                             cudaFuncAttributeMaxDynamicSharedMemorySize, CONV_SMEM);
        cudaFuncSetAttribute(qm_tc_kernel,
                             cudaFuncAttributeMaxDynamicSharedMemorySize, QM_SMEM);
        attr_done = true;
    }

    // fused preprocessing: 4096 wsplit + 4096 spike_t + 8 bn_prep blocks
    preproc_kernel<<<8200, 256>>>(x, qw, kw, vw, pw,
                                  qg, qb, qm, qv, kg, kb, km, kv,
                                  vg, vb, vm, vv, pg, pb, pm, pv);

    // fused q,k,v conv: M = 1536, tiles (16 n, 12 m, 8 b)  [R7 best config]
    conv_mma_kernel<true, true, __half><<<dim3(16, 12, 8), 256, CONV_SMEM>>>(
        wsp, xs_t, bns, bnb, q, k, v);

    ktv_mma_kernel<<<64, 256>>>();
    qm_tc_kernel<<<64, 256, QM_SMEM>>>();

    const size_t WS = (size_t)512 * 1024;
    conv_mma_kernel<false, false, float><<<dim3(16, 4, 8), 256, CONV_SMEM>>>(
        wsp + 3 * WS, os_t, bns + 3 * CH, bnb + 3 * CH, out, nullptr, nullptr);
}

// round 15
// speedup vs baseline: 1.0430x; 1.0430x over previous
#include <cuda_runtime.h>
#include <cuda_fp16.h>
#include <cstdint>

#define BATCH 8
#define CH    512
#define NPIX  1024
#define HEADS 8
#define HD    64
#define EPSBN 1e-5f

// ---------------- static scratch (no allocs allowed) ----------------
__device__ __half g_xs_t [BATCH * NPIX * CH];   // spiked x, transposed [b][n][c]
__device__ __half g_q    [BATCH * CH * NPIX];   // [b][c][n]
__device__ __half g_k    [BATCH * CH * NPIX];
__device__ __half g_v    [BATCH * CH * NPIX];
__device__ __half g_os_t [BATCH * NPIX * CH];   // spiked attn out, [b][n][c]
__device__ __half g_Msp  [BATCH * HEADS * 2 * HD * HD];  // [bh][hi/lo][d'][d]  (M^T split)
__device__ __half g_wsplit[4 * CH * (2 * CH)];  // per weight: [o][c<512]=hi, [o][512+c]=lo
__device__ float  g_bns[4 * CH];
__device__ float  g_bnb[4 * CH];

__device__ __forceinline__ float spikef(float x) {
    x = fminf(fmaxf(x, 0.0f), 4.0f);
    return rintf(x) * 0.25f;           // round-half-even == jnp.round
}

// ---------------- PTX helpers (baseline sm_80+ features only) ----------------
__device__ __forceinline__ uint32_t smem_u32(const void* p) {
    uint32_t a;
    asm("{ .reg .u64 t; cvta.to.shared.u64 t, %1; cvt.u32.u64 %0, t; }" : "=r"(a) : "l"(p));
    return a;
}
#define CP_ASYNC16(dst, src) \
    asm volatile("cp.async.cg.shared.global [%0], [%1], 16;" :: "r"(dst), "l"(src))
#define CP_COMMIT()  asm volatile("cp.async.commit_group;" ::: "memory")
#define CP_WAIT1()   asm volatile("cp.async.wait_group 1;" ::: "memory")
#define CP_WAIT0()   asm volatile("cp.async.wait_group 0;" ::: "memory")

__device__ __forceinline__ void ldsm_x4(uint32_t& r0, uint32_t& r1, uint32_t& r2, uint32_t& r3,
                                        uint32_t addr) {
    asm volatile("ldmatrix.sync.aligned.m8n8.x4.shared.b16 {%0,%1,%2,%3}, [%4];"
                 : "=r"(r0), "=r"(r1), "=r"(r2), "=r"(r3) : "r"(addr));
}
__device__ __forceinline__ void ldsm_x4_t(uint32_t& r0, uint32_t& r1, uint32_t& r2, uint32_t& r3,
                                          uint32_t addr) {
    asm volatile("ldmatrix.sync.aligned.m8n8.x4.trans.shared.b16 {%0,%1,%2,%3}, [%4];"
                 : "=r"(r0), "=r"(r1), "=r"(r2), "=r"(r3) : "r"(addr));
}
__device__ __forceinline__ void mma16816(float* d, const uint32_t* a, const uint32_t* b) {
    asm volatile(
        "mma.sync.aligned.m16n8k16.row.col.f32.f16.f16.f32 "
        "{%0,%1,%2,%3},{%4,%5,%6,%7},{%8,%9},{%0,%1,%2,%3};"
        : "+f"(d[0]), "+f"(d[1]), "+f"(d[2]), "+f"(d[3])
        : "r"(a[0]), "r"(a[1]), "r"(a[2]), "r"(a[3]), "r"(b[0]), "r"(b[1]));
}
#define SW128(off) ((off) ^ (((off) >> 3) & 0x70))

// ---------------------------------------------------------------------------
// K0: fused preprocessing: wsplit (bid<4096) | spike_t (4096..8191) | bn_prep
// ---------------------------------------------------------------------------
__global__ void preproc_kernel(
    const float* __restrict__ x,
    const float* __restrict__ w0, const float* __restrict__ w1,
    const float* __restrict__ w2, const float* __restrict__ w3,
    const float* __restrict__ qg, const float* __restrict__ qb,
    const float* __restrict__ qm, const float* __restrict__ qv,
    const float* __restrict__ kg, const float* __restrict__ kb,
    const float* __restrict__ km, const float* __restrict__ kv,
    const float* __restrict__ vg, const float* __restrict__ vb,
    const float* __restrict__ vm, const float* __restrict__ vv,
    const float* __restrict__ pg, const float* __restrict__ pb,
    const float* __restrict__ pm, const float* __restrict__ pv)
{
    __shared__ float tile[32][33];
    const int bid = blockIdx.x;
    const int tid = threadIdx.x;

    if (bid < 4096) {
        const float* W[4] = {w0, w1, w2, w3};
        int wi = bid >> 10;
        int idx = (bid & 1023) * 256 + tid;
        int o = idx >> 9, c = idx & 511;
        float w = W[wi][o * 512 + c];
        __half h1 = __float2half_rn(w);
        __half h2 = __float2half_rn(w - __half2float(h1));
        __half* dst = g_wsplit + (size_t)(wi * 512 + o) * 1024;
        dst[c]       = h1;
        dst[512 + c] = h2;
    } else if (bid < 8192) {
        int sid = bid - 4096;
        int n0 = (sid & 31) * 32, c0 = ((sid >> 5) & 15) * 32, b = sid >> 9;
        int tx = tid & 31, ty = tid >> 5;
        const float* xb = x + (size_t)b * CH * NPIX;
#pragma unroll
        for (int i = 0; i < 4; i++)
            tile[ty + i * 8][tx] = spikef(xb[(size_t)(c0 + ty + i * 8) * NPIX + n0 + tx]);
        __syncthreads();
        __half* ob = g_xs_t + (size_t)b * NPIX * CH;
#pragma unroll
        for (int i = 0; i < 4; i++)
            ob[(size_t)(n0 + ty + i * 8) * CH + c0 + tx] = __float2half_rn(tile[tx][ty + i * 8]);
    } else {
        int idx = (bid - 8192) * 256 + tid;      // 0..2047
        int wi = idx >> 9, c = idx & 511;
        const float* G[4] = {qg, kg, vg, pg};
        const float* Bb[4] = {qb, kb, vb, pb};
        const float* Mm[4] = {qm, km, vm, pm};
        const float* Vv[4] = {qv, kv, vv, pv};
        float s = G[wi][c] / sqrtf(Vv[wi][c] + EPSBN);
        g_bns[idx] = s;
        g_bnb[idx] = Bb[wi][c] - Mm[wi][c] * s;
    }
}

// ---------------------------------------------------------------------------
// K2: mma.sync conv_bn GEMM — R7 config (best measured). Tile M=128, N=64,
// BK=64, 3-stage cp.async, 8 warps (4m x 2n), warp tile 32x32, 3 CTAs/SM.
// ---------------------------------------------------------------------------
template <bool SPIKE, bool FUSED, typename OutT>
__global__ __launch_bounds__(256, 3)
void conv_mma_kernel(const __half* __restrict__ Wsp,   // [M][1024]
                     const __half* __restrict__ Bact,  // [B][1024][512]
                     const float* __restrict__ bns,
                     const float* __restrict__ bnb,
                     OutT* __restrict__ Yq, OutT* __restrict__ Yk, OutT* __restrict__ Yv)
{
    extern __shared__ char dsm[];
    const int tid  = threadIdx.x;
    const int wid  = tid >> 5, lane = tid & 31;
    const int b      = blockIdx.z;
    const int tile_n = blockIdx.x * 64;
    const int tile_m = blockIdx.y * 128;
    const int warp_m = (wid & 3) * 32;
    const int warp_n = (wid >> 2) * 32;

    OutT* Yb;
    if (FUSED) {
        const int wi = tile_m >> 9;
        Yb = (wi == 0) ? Yq : ((wi == 1) ? Yk : Yv);
    } else {
        Yb = Yq;
    }

    uint32_t base = (smem_u32(dsm) + 1023) & ~1023u;
    uint32_t sA[3], sB[3];
#pragma unroll
    for (int s = 0; s < 3; s++) { sA[s] = base + s * 24576; sB[s] = sA[s] + 16384; }

    const __half* Bb   = Bact + (size_t)b * NPIX * CH;
    const __half* Arow = Wsp + (size_t)(tile_m + (tid >> 1)) * 1024 + (tid & 1) * 32;
    const __half* Brow = Bb  + (size_t)(tile_n + (tid >> 2)) * 512  + (tid & 3) * 16;

    uint32_t stgA[4], stgB[2];
#pragma unroll
    for (int i = 0; i < 4; i++)
        stgA[i] = SW128((uint32_t)(tid >> 1) * 128 + ((tid & 1) * 4 + i) * 16);
#pragma unroll
    for (int i = 0; i < 2; i++)
        stgB[i] = SW128((uint32_t)(tid >> 2) * 128 + ((tid & 3) * 2 + i) * 16);

    const uint32_t aoff = (uint32_t)(warp_m + (lane & 15)) * 128 + (lane >> 4) * 16;
    const uint32_t boff = (uint32_t)(warp_n + ((lane >> 4) & 1) * 8 + (lane & 7)) * 128
                        + ((lane >> 3) & 1) * 16;

    float acc[2][4][4];
#pragma unroll
    for (int mt = 0; mt < 2; mt++)
#pragma unroll
        for (int nt = 0; nt < 4; nt++)
#pragma unroll
            for (int e = 0; e < 4; e++) acc[mt][nt][e] = 0.0f;

#pragma unroll
    for (int st = 0; st < 2; st++) {
#pragma unroll
        for (int i = 0; i < 4; i++) CP_ASYNC16(sA[st] + stgA[i], Arow + st * 64 + i * 8);
#pragma unroll
        for (int i = 0; i < 2; i++) CP_ASYNC16(sB[st] + stgB[i], Brow + st * 64 + i * 8);
        CP_COMMIT();
    }
    CP_WAIT1();
    __syncthreads();

#pragma unroll 1
    for (int ch = 0; ch < 16; ch++) {
        if (ch < 14) {
            const int st = (ch + 2) % 3;
            const __half* An = Arow + (size_t)(ch + 2) * 64;
            const __half* Bn = Brow + (size_t)((ch + 2) & 7) * 64;
#pragma unroll
            for (int i = 0; i < 4; i++) CP_ASYNC16(sA[st] + stgA[i], An + i * 8);
#pragma unroll
            for (int i = 0; i < 2; i++) CP_ASYNC16(sB[st] + stgB[i], Bn + i * 8);
            CP_COMMIT();
        }

        const uint32_t A0 = sA[ch % 3], B0 = sB[ch % 3];
#pragma unroll
        for (int s = 0; s < 4; s++) {
            uint32_t af[2][4], bf[2][4];
#pragma unroll
            for (int mt = 0; mt < 2; mt++)
                ldsm_x4(af[mt][0], af[mt][1], af[mt][2], af[mt][3],
                        A0 + SW128(aoff + mt * 2048 + s * 32));
#pragma unroll
            for (int p = 0; p < 2; p++)
                ldsm_x4(bf[p][0], bf[p][1], bf[p][2], bf[p][3],
                        B0 + SW128(boff + p * 2048 + s * 32));
#pragma unroll
            for (int mt = 0; mt < 2; mt++)
#pragma unroll
                for (int nt = 0; nt < 4; nt++)
                    mma16816(acc[mt][nt], af[mt], &bf[nt >> 1][(nt & 1) * 2]);
        }

        if (ch < 15) {
            if (ch < 14) { CP_WAIT1(); } else { CP_WAIT0(); }
            __syncthreads();
        }
    }

    const int r0 = lane >> 2;
    const int c0 = (lane & 3) * 2;
#pragma unroll
    for (int mt = 0; mt < 2; mt++) {
#pragma unroll
        for (int half = 0; half < 2; half++) {
            const int o = tile_m + warp_m + mt * 16 + r0 + half * 8;
            const float s    = bns[o];
            const float beta = bnb[o];
            OutT* yrow = Yb + ((size_t)b * 512 + (o & 511)) * 1024;
#pragma unroll
            for (int nt = 0; nt < 4; nt++) {
                const int n = tile_n + warp_n + nt * 8 + c0;
                float y0 = fmaf(acc[mt][nt][half * 2 + 0], s, beta);
                float y1 = fmaf(acc[mt][nt][half * 2 + 1], s, beta);
                if (SPIKE) {
                    __half2 hh = __floats2half2_rn(spikef(y0), spikef(y1));
                    *reinterpret_cast<__half2*>((__half*)yrow + n) = hh;
                } else {
                    *reinterpret_cast<float2*>((float*)yrow + n) = make_float2(y0, y1);
                }
            }
        }
    }
}

// ---------------------------------------------------------------------------
// K3: ktv via mma.sync, ONE block per bh, 256 threads (8 warps: 2 d x 4 d',
// warp tile 32x16). K=1024 in-block, exact fp32 sums. Epilogue writes M^T
// split hi/lo fp16 (exact: M multiples of 1/16, |M|<=1024 -> <=14 sig bits).
// ---------------------------------------------------------------------------
__global__ __launch_bounds__(256)
void ktv_mma_kernel() {
    __shared__ char sm[2 * 16384];
    const int tid = threadIdx.x;
    const int wid = tid >> 5, lane = tid & 31;
    const int bh = blockIdx.x;
    const int b = bh >> 3, h = bh & 7;
    const int warp_m = (wid & 1) * 32;      // d rows
    const int warp_n = (wid >> 1) * 16;     // d' rows

    uint32_t base = smem_u32(sm);
    uint32_t sK[2] = {base,         base + 8192};
    uint32_t sV[2] = {base + 16384, base + 24576};

    const __half* Kb = g_k + (size_t)b * CH * NPIX + (size_t)h * HD * NPIX;
    const __half* Vb = g_v + (size_t)b * CH * NPIX + (size_t)h * HD * NPIX;

    const int srow = tid >> 2, scb = (tid & 3) * 2;
    const __half* Krow = Kb + (size_t)srow * NPIX + scb * 8;
    const __half* Vrow = Vb + (size_t)srow * NPIX + scb * 8;
    uint32_t stg[2];
#pragma unroll
    for (int j = 0; j < 2; j++)
        stg[j] = SW128((uint32_t)srow * 128 + (scb + j) * 16);

    const uint32_t aoff = (uint32_t)(warp_m + (lane & 15)) * 128 + (lane >> 4) * 16;
    const uint32_t boff = (uint32_t)(warp_n + ((lane >> 4) & 1) * 8 + (lane & 7)) * 128
                        + ((lane >> 3) & 1) * 16;

    float acc[2][2][4];
#pragma unroll
    for (int mt = 0; mt < 2; mt++)
#pragma unroll
        for (int nt = 0; nt < 2; nt++)
#pragma unroll
            for (int e = 0; e < 4; e++) acc[mt][nt][e] = 0.0f;

#pragma unroll
    for (int j = 0; j < 2; j++) {
        CP_ASYNC16(sK[0] + stg[j], Krow + j * 8);
        CP_ASYNC16(sV[0] + stg[j], Vrow + j * 8);
    }
    CP_COMMIT();

#pragma unroll 1
    for (int ch = 0; ch < 16; ch++) {
        __syncthreads();
        if (ch < 15) {
            const int st = (ch + 1) & 1;
#pragma unroll
            for (int j = 0; j < 2; j++) {
                CP_ASYNC16(sK[st] + stg[j], Krow + (ch + 1) * 64 + j * 8);
                CP_ASYNC16(sV[st] + stg[j], Vrow + (ch + 1) * 64 + j * 8);
            }
            CP_COMMIT();
            CP_WAIT1();
        } else {
            CP_WAIT0();
        }
        __syncthreads();

        const uint32_t A0 = sK[ch & 1], B0 = sV[ch & 1];
#pragma unroll
        for (int s = 0; s < 4; s++) {
            uint32_t af[2][4], bf[4];
#pragma unroll
            for (int mt = 0; mt < 2; mt++)
                ldsm_x4(af[mt][0], af[mt][1], af[mt][2], af[mt][3],
                        A0 + SW128(aoff + mt * 2048 + s * 32));
            ldsm_x4(bf[0], bf[1], bf[2], bf[3], B0 + SW128(boff + s * 32));
#pragma unroll
            for (int mt = 0; mt < 2; mt++)
#pragma unroll
                for (int nt = 0; nt < 2; nt++)
                    mma16816(acc[mt][nt], af[mt], &bf[nt * 2]);
        }
    }

    __half* Mp = g_Msp + (size_t)bh * 8192;
    const int r0 = lane >> 2, c0 = (lane & 3) * 2;
#pragma unroll
    for (int mt = 0; mt < 2; mt++)
#pragma unroll
        for (int half = 0; half < 2; half++) {
            const int d = warp_m + mt * 16 + r0 + half * 8;
#pragma unroll
            for (int nt = 0; nt < 2; nt++) {
#pragma unroll
                for (int e = 0; e < 2; e++) {
                    const int dp = warp_n + nt * 8 + c0 + e;
                    float v = acc[mt][nt][half * 2 + e];
                    __half hi = __float2half_rn(v);
                    __half lo = __float2half_rn(v - __half2float(hi));
                    Mp[dp * 64 + d]        = hi;
                    Mp[4096 + dp * 64 + d] = lo;
                }
            }
        }
}

// ---------------------------------------------------------------------------
// K4: qm via mma.sync. grid (4 nsplit, 64 bh) = 256 CTAs, 2 n-tiles per CTA,
// double-buffered cp.async q staging; Msp loaded once per CTA (2x reuse).
// D[d'][n] = sum_d (Mhi+Mlo)^T[d'][d] * q[d][n]; os_t = fp16(spike(0.25*D)).
// smem: [0,16K) Msp | [16K,32K) qbuf0 | [32K,48K) qbuf1 | [48K,+16.5K) ds
// ---------------------------------------------------------------------------
static constexpr int QM_SMEM = 49152 + 64 * 132 * 2;   // 66048

__global__ __launch_bounds__(256)
void qm_tc_kernel() {
    extern __shared__ __align__(16) char qsm[];
    const int tid = threadIdx.x;
    const int wid = tid >> 5, lane = tid & 31;
    const int nbase = blockIdx.x * 2;          // first of 2 n-tiles for this CTA
    const int bh = blockIdx.y;
    const int b = bh >> 3, h = bh & 7;
    const uint32_t base = smem_u32(qsm);
    const uint32_t QB[2] = {base + 16384, base + 32768};
    __half* ds = (__half*)(qsm + 49152);

    // stage Msp once: 2 planes x 64 rows(d') x 128B, SW128 within plane
    const int4* gmsp = (const int4*)(g_Msp + (size_t)bh * 8192);
#pragma unroll
    for (int l = 0; l < 4; l++) {
        int i = tid + l * 256;                 // 0..1023 16B chunks
        int j = i & 511;
        uint32_t off = (uint32_t)(i >> 9) * 8192 + SW128((uint32_t)(j >> 3) * 128 + (j & 7) * 16);
        *(int4*)(qsm + off) = gmsp[i];
    }

    const __half* Qb = g_q + (size_t)b * CH * NPIX + (size_t)h * HD * NPIX;

    // prologue: tile nbase -> buf 0
#pragma unroll
    for (int l = 0; l < 4; l++) {
        int i = tid + l * 256;
        int s = i >> 9, j = i & 511;
        int d = j >> 3, c = j & 7;
        uint32_t off = QB[0] + (uint32_t)s * 8192 + SW128((uint32_t)d * 128 + c * 16);
        CP_ASYNC16(off, Qb + (size_t)d * NPIX + nbase * 128 + s * 64 + c * 8);
    }
    CP_COMMIT();

    const int warp_m = (wid & 1) * 32;                      // d' range
    const int wn = wid >> 1;                                // 0..3, n base = wn*32
    const int r0 = lane >> 2, c0 = (lane & 3) * 2;

#pragma unroll 1
    for (int t = 0; t < 2; t++) {
        const int nt = nbase + t;
        if (t == 0) {
            // prefetch second tile into buf 1
#pragma unroll
            for (int l = 0; l < 4; l++) {
                int i = tid + l * 256;
                int s = i >> 9, j = i & 511;
                int d = j >> 3, c = j & 7;
                uint32_t off = QB[1] + (uint32_t)s * 8192 + SW128((uint32_t)d * 128 + c * 16);
                CP_ASYNC16(off, Qb + (size_t)d * NPIX + (nbase + 1) * 128 + s * 64 + c * 8);
            }
            CP_COMMIT();
            CP_WAIT1();        // tile nbase's group drained
        } else {
            CP_WAIT0();        // tile nbase+1 drained
        }
        __syncthreads();       // publish tile (and Msp on first iter)

        const uint32_t qsub = QB[t] + (uint32_t)(wn >> 1) * 8192;
        const uint32_t colb = (uint32_t)(wn & 1) * 64;

        float acc[2][4][4];
#pragma unroll
        for (int mt = 0; mt < 2; mt++)
#pragma unroll
            for (int nn = 0; nn < 4; nn++)
#pragma unroll
                for (int e = 0; e < 4; e++) acc[mt][nn][e] = 0.0f;

#pragma unroll
        for (int plane = 0; plane < 2; plane++) {
            const uint32_t Ab = base + plane * 8192;
#pragma unroll
            for (int s = 0; s < 4; s++) {
                uint32_t af[2][4], bf[2][4];
#pragma unroll
                for (int mt = 0; mt < 2; mt++)
                    ldsm_x4(af[mt][0], af[mt][1], af[mt][2], af[mt][3],
                            Ab + SW128((uint32_t)(warp_m + mt * 16 + (lane & 15)) * 128
                                       + s * 32 + (lane >> 4) * 16));
                const int krow = s * 16 + (lane & 7) + ((lane >> 3) & 1) * 8;
#pragma unroll
                for (int nb = 0; nb < 2; nb++)
                    ldsm_x4_t(bf[nb][0], bf[nb][1], bf[nb][2], bf[nb][3],
                              qsub + SW128((uint32_t)krow * 128 + colb + nb * 32
                                           + (lane >> 4) * 16));
#pragma unroll
                for (int mt = 0; mt < 2; mt++)
#pragma unroll
                    for (int nn = 0; nn < 4; nn++)
                        mma16816(acc[mt][nn], af[mt], &bf[nn >> 1][(nn & 1) * 2]);
            }
        }

        // epilogue: spike(0.25*D) -> ds -> coalesced os_t rows
#pragma unroll
        for (int mt = 0; mt < 2; mt++)
#pragma unroll
            for (int half = 0; half < 2; half++) {
                const int dp = warp_m + mt * 16 + r0 + half * 8;
#pragma unroll
                for (int nn = 0; nn < 4; nn++) {
                    const int nloc = wn * 32 + nn * 8 + c0;
                    float y0 = spikef(acc[mt][nn][half * 2 + 0] * 0.25f);
                    float y1 = spikef(acc[mt][nn][half * 2 + 1] * 0.25f);
                    *reinterpret_cast<__half2*>(ds + dp * 132 + nloc) =
                        __floats2half2_rn(y0, y1);
                }
            }
        __syncthreads();

        if (tid < 128) {
            __half hv[64];
#pragma unroll
            for (int dp = 0; dp < 64; dp++) hv[dp] = ds[dp * 132 + tid];
            __half* Ob = g_os_t + (size_t)b * NPIX * CH
                       + (size_t)(nt * 128 + tid) * CH + h * 64;
#pragma unroll
            for (int i = 0; i < 8; i++)
                *reinterpret_cast<int4*>(Ob + i * 8) = reinterpret_cast<int4*>(hv)[i];
        }
        if (t == 0) __syncthreads();   // ds free before next iter's epilogue writes
    }
}

// ---------------------------------------------------------------------------
// launch
// ---------------------------------------------------------------------------
static constexpr int CONV_SMEM = 3 * 24576 + 1024;   // 74752

extern "C" void kernel_launch(void* const* d_in, const int* in_sizes, int n_in,
                              void* d_out, int out_size) {
    (void)in_sizes; (void)n_in; (void)out_size;
    const float* x  = (const float*)d_in[0];
    const float* qw = (const float*)d_in[1];
    const float* qg = (const float*)d_in[2];
    const float* qb = (const float*)d_in[3];
    const float* qm = (const float*)d_in[4];
    const float* qv = (const float*)d_in[5];
    const float* kw = (const float*)d_in[6];
    const float* kg = (const float*)d_in[7];
    const float* kb = (const float*)d_in[8];
    const float* km = (const float*)d_in[9];
    const float* kv = (const float*)d_in[10];
    const float* vw = (const float*)d_in[11];
    const float* vg = (const float*)d_in[12];
    const float* vb = (const float*)d_in[13];
    const float* vm = (const float*)d_in[14];
    const float* vv = (const float*)d_in[15];
    const float* pw = (const float*)d_in[16];
    const float* pg = (const float*)d_in[17];
    const float* pb = (const float*)d_in[18];
    const float* pm = (const float*)d_in[19];
    const float* pv = (const float*)d_in[20];
    float* out = (float*)d_out;

    __half *xs_t, *q, *k, *v, *os_t, *wsp;
    float *bns, *bnb;
    cudaGetSymbolAddress((void**)&xs_t, g_xs_t);
    cudaGetSymbolAddress((void**)&q,    g_q);
    cudaGetSymbolAddress((void**)&k,    g_k);
    cudaGetSymbolAddress((void**)&v,    g_v);
    cudaGetSymbolAddress((void**)&os_t, g_os_t);
    cudaGetSymbolAddress((void**)&wsp,  g_wsplit);
    cudaGetSymbolAddress((void**)&bns,  g_bns);
    cudaGetSymbolAddress((void**)&bnb,  g_bnb);

    static bool attr_done = false;
    if (!attr_done) {
        cudaFuncSetAttribute(conv_mma_kernel<true,  true,  __half>,
                             cudaFuncAttributeMaxDynamicSharedMemorySize, CONV_SMEM);
        cudaFuncSetAttribute(conv_mma_kernel<false, false, float>,
                             cudaFuncAttributeMaxDynamicSharedMemorySize, CONV_SMEM);
        cudaFuncSetAttribute(qm_tc_kernel,
                             cudaFuncAttributeMaxDynamicSharedMemorySize, QM_SMEM);
        attr_done = true;
    }

    // fused preprocessing: 4096 wsplit + 4096 spike_t + 8 bn_prep blocks
    preproc_kernel<<<8200, 256>>>(x, qw, kw, vw, pw,
                                  qg, qb, qm, qv, kg, kb, km, kv,
                                  vg, vb, vm, vv, pg, pb, pm, pv);

    // fused q,k,v conv: M = 1536, tiles (16 n, 12 m, 8 b)  [R7 best config]
    conv_mma_kernel<true, true, __half><<<dim3(16, 12, 8), 256, CONV_SMEM>>>(
        wsp, xs_t, bns, bnb, q, k, v);

    ktv_mma_kernel<<<64, 256>>>();
    qm_tc_kernel<<<dim3(4, 64), 256, QM_SMEM>>>();

    const size_t WS = (size_t)512 * 1024;
    conv_mma_kernel<false, false, float><<<dim3(16, 4, 8), 256, CONV_SMEM>>>(
        wsp + 3 * WS, os_t, bns + 3 * CH, bnb + 3 * CH, out, nullptr, nullptr);
}

// round 16
// speedup vs baseline: 1.0632x; 1.0194x over previous
#include <cuda_runtime.h>
#include <cuda_fp16.h>
#include <cstdint>

#define BATCH 8
#define CH    512
#define NPIX  1024
#define HEADS 8
#define HD    64
#define EPSBN 1e-5f

// ---------------- static scratch (no allocs allowed) ----------------
__device__ __half g_xs_t [BATCH * NPIX * CH];   // spiked x, transposed [b][n][c]
__device__ __half g_q    [BATCH * CH * NPIX];   // [b][c][n]
__device__ __half g_k    [BATCH * CH * NPIX];
__device__ __half g_v    [BATCH * CH * NPIX];
__device__ __half g_os_t [BATCH * NPIX * CH];   // spiked attn out, [b][n][c]
__device__ float  g_Mpart[2 * BATCH * HEADS * HD * HD];  // [ns][bh][d'][d] fp32 partials
__device__ __half g_wsplit[4 * CH * (2 * CH)];  // per weight: [o][c<512]=hi, [o][512+c]=lo
__device__ float  g_bns[4 * CH];
__device__ float  g_bnb[4 * CH];

__device__ __forceinline__ float spikef(float x) {
    x = fminf(fmaxf(x, 0.0f), 4.0f);
    return rintf(x) * 0.25f;           // round-half-even == jnp.round
}

// ---------------- PTX helpers (baseline sm_80+ features only) ----------------
__device__ __forceinline__ uint32_t smem_u32(const void* p) {
    uint32_t a;
    asm("{ .reg .u64 t; cvta.to.shared.u64 t, %1; cvt.u32.u64 %0, t; }" : "=r"(a) : "l"(p));
    return a;
}
#define CP_ASYNC16(dst, src) \
    asm volatile("cp.async.cg.shared.global [%0], [%1], 16;" :: "r"(dst), "l"(src))
#define CP_COMMIT()  asm volatile("cp.async.commit_group;" ::: "memory")
#define CP_WAIT1()   asm volatile("cp.async.wait_group 1;" ::: "memory")
#define CP_WAIT0()   asm volatile("cp.async.wait_group 0;" ::: "memory")

__device__ __forceinline__ void ldsm_x4(uint32_t& r0, uint32_t& r1, uint32_t& r2, uint32_t& r3,
                                        uint32_t addr) {
    asm volatile("ldmatrix.sync.aligned.m8n8.x4.shared.b16 {%0,%1,%2,%3}, [%4];"
                 : "=r"(r0), "=r"(r1), "=r"(r2), "=r"(r3) : "r"(addr));
}
__device__ __forceinline__ void ldsm_x4_t(uint32_t& r0, uint32_t& r1, uint32_t& r2, uint32_t& r3,
                                          uint32_t addr) {
    asm volatile("ldmatrix.sync.aligned.m8n8.x4.trans.shared.b16 {%0,%1,%2,%3}, [%4];"
                 : "=r"(r0), "=r"(r1), "=r"(r2), "=r"(r3) : "r"(addr));
}
__device__ __forceinline__ void mma16816(float* d, const uint32_t* a, const uint32_t* b) {
    asm volatile(
        "mma.sync.aligned.m16n8k16.row.col.f32.f16.f16.f32 "
        "{%0,%1,%2,%3},{%4,%5,%6,%7},{%8,%9},{%0,%1,%2,%3};"
        : "+f"(d[0]), "+f"(d[1]), "+f"(d[2]), "+f"(d[3])
        : "r"(a[0]), "r"(a[1]), "r"(a[2]), "r"(a[3]), "r"(b[0]), "r"(b[1]));
}
#define SW128(off) ((off) ^ (((off) >> 3) & 0x70))

// ---------------------------------------------------------------------------
// K0: fused preprocessing: wsplit (bid<4096) | spike_t (4096..8191) | bn_prep
// ---------------------------------------------------------------------------
__global__ void preproc_kernel(
    const float* __restrict__ x,
    const float* __restrict__ w0, const float* __restrict__ w1,
    const float* __restrict__ w2, const float* __restrict__ w3,
    const float* __restrict__ qg, const float* __restrict__ qb,
    const float* __restrict__ qm, const float* __restrict__ qv,
    const float* __restrict__ kg, const float* __restrict__ kb,
    const float* __restrict__ km, const float* __restrict__ kv,
    const float* __restrict__ vg, const float* __restrict__ vb,
    const float* __restrict__ vm, const float* __restrict__ vv,
    const float* __restrict__ pg, const float* __restrict__ pb,
    const float* __restrict__ pm, const float* __restrict__ pv)
{
    __shared__ float tile[32][33];
    const int bid = blockIdx.x;
    const int tid = threadIdx.x;

    if (bid < 4096) {
        const float* W[4] = {w0, w1, w2, w3};
        int wi = bid >> 10;
        int idx = (bid & 1023) * 256 + tid;
        int o = idx >> 9, c = idx & 511;
        float w = W[wi][o * 512 + c];
        __half h1 = __float2half_rn(w);
        __half h2 = __float2half_rn(w - __half2float(h1));
        __half* dst = g_wsplit + (size_t)(wi * 512 + o) * 1024;
        dst[c]       = h1;
        dst[512 + c] = h2;
    } else if (bid < 8192) {
        int sid = bid - 4096;
        int n0 = (sid & 31) * 32, c0 = ((sid >> 5) & 15) * 32, b = sid >> 9;
        int tx = tid & 31, ty = tid >> 5;
        const float* xb = x + (size_t)b * CH * NPIX;
#pragma unroll
        for (int i = 0; i < 4; i++)
            tile[ty + i * 8][tx] = spikef(xb[(size_t)(c0 + ty + i * 8) * NPIX + n0 + tx]);
        __syncthreads();
        __half* ob = g_xs_t + (size_t)b * NPIX * CH;
#pragma unroll
        for (int i = 0; i < 4; i++)
            ob[(size_t)(n0 + ty + i * 8) * CH + c0 + tx] = __float2half_rn(tile[tx][ty + i * 8]);
    } else {
        int idx = (bid - 8192) * 256 + tid;      // 0..2047
        int wi = idx >> 9, c = idx & 511;
        const float* G[4] = {qg, kg, vg, pg};
        const float* Bb[4] = {qb, kb, vb, pb};
        const float* Mm[4] = {qm, km, vm, pm};
        const float* Vv[4] = {qv, kv, vv, pv};
        float s = G[wi][c] / sqrtf(Vv[wi][c] + EPSBN);
        g_bns[idx] = s;
        g_bnb[idx] = Bb[wi][c] - Mm[wi][c] * s;
    }
}

// ---------------------------------------------------------------------------
// K2: mma.sync conv_bn GEMM — R7 config (best measured). Tile M=128, N=64,
// BK=64, 3-stage cp.async, 8 warps (4m x 2n), warp tile 32x32, 3 CTAs/SM.
// ---------------------------------------------------------------------------
template <bool SPIKE, bool FUSED, typename OutT>
__global__ __launch_bounds__(256, 3)
void conv_mma_kernel(const __half* __restrict__ Wsp,   // [M][1024]
                     const __half* __restrict__ Bact,  // [B][1024][512]
                     const float* __restrict__ bns,
                     const float* __restrict__ bnb,
                     OutT* __restrict__ Yq, OutT* __restrict__ Yk, OutT* __restrict__ Yv)
{
    extern __shared__ char dsm[];
    const int tid  = threadIdx.x;
    const int wid  = tid >> 5, lane = tid & 31;
    const int b      = blockIdx.z;
    const int tile_n = blockIdx.x * 64;
    const int tile_m = blockIdx.y * 128;
    const int warp_m = (wid & 3) * 32;
    const int warp_n = (wid >> 2) * 32;

    OutT* Yb;
    if (FUSED) {
        const int wi = tile_m >> 9;
        Yb = (wi == 0) ? Yq : ((wi == 1) ? Yk : Yv);
    } else {
        Yb = Yq;
    }

    uint32_t base = (smem_u32(dsm) + 1023) & ~1023u;
    uint32_t sA[3], sB[3];
#pragma unroll
    for (int s = 0; s < 3; s++) { sA[s] = base + s * 24576; sB[s] = sA[s] + 16384; }

    const __half* Bb   = Bact + (size_t)b * NPIX * CH;
    const __half* Arow = Wsp + (size_t)(tile_m + (tid >> 1)) * 1024 + (tid & 1) * 32;
    const __half* Brow = Bb  + (size_t)(tile_n + (tid >> 2)) * 512  + (tid & 3) * 16;

    uint32_t stgA[4], stgB[2];
#pragma unroll
    for (int i = 0; i < 4; i++)
        stgA[i] = SW128((uint32_t)(tid >> 1) * 128 + ((tid & 1) * 4 + i) * 16);
#pragma unroll
    for (int i = 0; i < 2; i++)
        stgB[i] = SW128((uint32_t)(tid >> 2) * 128 + ((tid & 3) * 2 + i) * 16);

    const uint32_t aoff = (uint32_t)(warp_m + (lane & 15)) * 128 + (lane >> 4) * 16;
    const uint32_t boff = (uint32_t)(warp_n + ((lane >> 4) & 1) * 8 + (lane & 7)) * 128
                        + ((lane >> 3) & 1) * 16;

    float acc[2][4][4];
#pragma unroll
    for (int mt = 0; mt < 2; mt++)
#pragma unroll
        for (int nt = 0; nt < 4; nt++)
#pragma unroll
            for (int e = 0; e < 4; e++) acc[mt][nt][e] = 0.0f;

#pragma unroll
    for (int st = 0; st < 2; st++) {
#pragma unroll
        for (int i = 0; i < 4; i++) CP_ASYNC16(sA[st] + stgA[i], Arow + st * 64 + i * 8);
#pragma unroll
        for (int i = 0; i < 2; i++) CP_ASYNC16(sB[st] + stgB[i], Brow + st * 64 + i * 8);
        CP_COMMIT();
    }
    CP_WAIT1();
    __syncthreads();

#pragma unroll 1
    for (int ch = 0; ch < 16; ch++) {
        if (ch < 14) {
            const int st = (ch + 2) % 3;
            const __half* An = Arow + (size_t)(ch + 2) * 64;
            const __half* Bn = Brow + (size_t)((ch + 2) & 7) * 64;
#pragma unroll
            for (int i = 0; i < 4; i++) CP_ASYNC16(sA[st] + stgA[i], An + i * 8);
#pragma unroll
            for (int i = 0; i < 2; i++) CP_ASYNC16(sB[st] + stgB[i], Bn + i * 8);
            CP_COMMIT();
        }

        const uint32_t A0 = sA[ch % 3], B0 = sB[ch % 3];
#pragma unroll
        for (int s = 0; s < 4; s++) {
            uint32_t af[2][4], bf[2][4];
#pragma unroll
            for (int mt = 0; mt < 2; mt++)
                ldsm_x4(af[mt][0], af[mt][1], af[mt][2], af[mt][3],
                        A0 + SW128(aoff + mt * 2048 + s * 32));
#pragma unroll
            for (int p = 0; p < 2; p++)
                ldsm_x4(bf[p][0], bf[p][1], bf[p][2], bf[p][3],
                        B0 + SW128(boff + p * 2048 + s * 32));
#pragma unroll
            for (int mt = 0; mt < 2; mt++)
#pragma unroll
                for (int nt = 0; nt < 4; nt++)
                    mma16816(acc[mt][nt], af[mt], &bf[nt >> 1][(nt & 1) * 2]);
        }

        if (ch < 15) {
            if (ch < 14) { CP_WAIT1(); } else { CP_WAIT0(); }
            __syncthreads();
        }
    }

    const int r0 = lane >> 2;
    const int c0 = (lane & 3) * 2;
#pragma unroll
    for (int mt = 0; mt < 2; mt++) {
#pragma unroll
        for (int half = 0; half < 2; half++) {
            const int o = tile_m + warp_m + mt * 16 + r0 + half * 8;
            const float s    = bns[o];
            const float beta = bnb[o];
            OutT* yrow = Yb + ((size_t)b * 512 + (o & 511)) * 1024;
#pragma unroll
            for (int nt = 0; nt < 4; nt++) {
                const int n = tile_n + warp_n + nt * 8 + c0;
                float y0 = fmaf(acc[mt][nt][half * 2 + 0], s, beta);
                float y1 = fmaf(acc[mt][nt][half * 2 + 1], s, beta);
                if (SPIKE) {
                    __half2 hh = __floats2half2_rn(spikef(y0), spikef(y1));
                    *reinterpret_cast<__half2*>((__half*)yrow + n) = hh;
                } else {
                    *reinterpret_cast<float2*>((float*)yrow + n) = make_float2(y0, y1);
                }
            }
        }
    }
}

// ---------------------------------------------------------------------------
// K3: ktv via mma.sync, split-K=2. grid (2 ns, 64 bh), 256 thr (8 warps:
// 2 d x 4 d', warp tile 32x16). K=512 per CTA, exact fp32 sums. Epilogue
// writes fp32 TRANSPOSED partial: g_Mpart[ns][bh][d'][d] (exact).
// ---------------------------------------------------------------------------
__global__ __launch_bounds__(256)
void ktv_mma_kernel() {
    __shared__ char sm[2 * 16384];
    const int tid = threadIdx.x;
    const int wid = tid >> 5, lane = tid & 31;
    const int ns = blockIdx.x, bh = blockIdx.y;
    const int b = bh >> 3, h = bh & 7;
    const int warp_m = (wid & 1) * 32;      // d rows
    const int warp_n = (wid >> 1) * 16;     // d' rows

    uint32_t base = smem_u32(sm);
    uint32_t sK[2] = {base,         base + 8192};
    uint32_t sV[2] = {base + 16384, base + 24576};

    const __half* Kb = g_k + (size_t)b * CH * NPIX + (size_t)h * HD * NPIX + ns * 512;
    const __half* Vb = g_v + (size_t)b * CH * NPIX + (size_t)h * HD * NPIX + ns * 512;

    const int srow = tid >> 2, scb = (tid & 3) * 2;
    const __half* Krow = Kb + (size_t)srow * NPIX + scb * 8;
    const __half* Vrow = Vb + (size_t)srow * NPIX + scb * 8;
    uint32_t stg[2];
#pragma unroll
    for (int j = 0; j < 2; j++)
        stg[j] = SW128((uint32_t)srow * 128 + (scb + j) * 16);

    const uint32_t aoff = (uint32_t)(warp_m + (lane & 15)) * 128 + (lane >> 4) * 16;
    const uint32_t boff = (uint32_t)(warp_n + ((lane >> 4) & 1) * 8 + (lane & 7)) * 128
                        + ((lane >> 3) & 1) * 16;

    float acc[2][2][4];
#pragma unroll
    for (int mt = 0; mt < 2; mt++)
#pragma unroll
        for (int nt = 0; nt < 2; nt++)
#pragma unroll
            for (int e = 0; e < 4; e++) acc[mt][nt][e] = 0.0f;

#pragma unroll
    for (int j = 0; j < 2; j++) {
        CP_ASYNC16(sK[0] + stg[j], Krow + j * 8);
        CP_ASYNC16(sV[0] + stg[j], Vrow + j * 8);
    }
    CP_COMMIT();

#pragma unroll 1
    for (int ch = 0; ch < 8; ch++) {
        __syncthreads();
        if (ch < 7) {
            const int st = (ch + 1) & 1;
#pragma unroll
            for (int j = 0; j < 2; j++) {
                CP_ASYNC16(sK[st] + stg[j], Krow + (ch + 1) * 64 + j * 8);
                CP_ASYNC16(sV[st] + stg[j], Vrow + (ch + 1) * 64 + j * 8);
            }
            CP_COMMIT();
            CP_WAIT1();
        } else {
            CP_WAIT0();
        }
        __syncthreads();

        const uint32_t A0 = sK[ch & 1], B0 = sV[ch & 1];
#pragma unroll
        for (int s = 0; s < 4; s++) {
            uint32_t af[2][4], bf[4];
#pragma unroll
            for (int mt = 0; mt < 2; mt++)
                ldsm_x4(af[mt][0], af[mt][1], af[mt][2], af[mt][3],
                        A0 + SW128(aoff + mt * 2048 + s * 32));
            ldsm_x4(bf[0], bf[1], bf[2], bf[3], B0 + SW128(boff + s * 32));
#pragma unroll
            for (int mt = 0; mt < 2; mt++)
#pragma unroll
                for (int nt = 0; nt < 2; nt++)
                    mma16816(acc[mt][nt], af[mt], &bf[nt * 2]);
        }
    }

    // epilogue: transposed fp32 partial store
    float* Mp = g_Mpart + ((size_t)ns * 64 + bh) * 4096;
    const int r0 = lane >> 2, c0 = (lane & 3) * 2;
#pragma unroll
    for (int mt = 0; mt < 2; mt++)
#pragma unroll
        for (int half = 0; half < 2; half++) {
            const int d = warp_m + mt * 16 + r0 + half * 8;
#pragma unroll
            for (int nt = 0; nt < 2; nt++) {
#pragma unroll
                for (int e = 0; e < 2; e++) {
                    const int dp = warp_n + nt * 8 + c0 + e;
                    Mp[dp * 64 + d] = acc[mt][nt][half * 2 + e];
                }
            }
        }
}

// ---------------------------------------------------------------------------
// K4: qm via mma.sync. grid (4 nsplit, 64 bh) = 256 CTAs, 2 n-tiles per CTA,
// double-buffered cp.async q staging. Staging SUMS the 2 fp32 ktv partials
// and splits hi/lo fp16 on the fly (exact: M <=14 sig bits = 11+3).
// D[d'][n] = sum_d (Mhi+Mlo)^T[d'][d] * q[d][n]; os_t = fp16(spike(0.25*D)).
// smem: [0,16K) Msp planes | [16K,32K) qbuf0 | [32K,48K) qbuf1 | [48K,+16.5K) ds
// ---------------------------------------------------------------------------
static constexpr int QM_SMEM = 49152 + 64 * 132 * 2;   // 66048

__global__ __launch_bounds__(256)
void qm_tc_kernel() {
    extern __shared__ __align__(16) char qsm[];
    const int tid = threadIdx.x;
    const int wid = tid >> 5, lane = tid & 31;
    const int nbase = blockIdx.x * 2;          // first of 2 n-tiles for this CTA
    const int bh = blockIdx.y;
    const int b = bh >> 3, h = bh & 7;
    const uint32_t base = smem_u32(qsm);
    const uint32_t QB[2] = {base + 16384, base + 32768};
    __half* ds = (__half*)(qsm + 49152);

    // stage Msp: sum 2 fp32 partials, split hi/lo, SW128 within each plane.
    // chunk i covers flat values f=i*4..i*4+3 -> d'=i>>4, d=(i&15)*4,
    // byte off in plane = d'*128 + d*2 (8B, swizzle-safe: bits<4 untouched)
    const float4* P0 = (const float4*)(g_Mpart + (size_t)bh * 4096);
    const float4* P1 = (const float4*)(g_Mpart + (size_t)(64 + bh) * 4096);
#pragma unroll
    for (int l = 0; l < 4; l++) {
        int i = tid + l * 256;                 // 0..1023 float4 chunks
        float4 a = P0[i], c = P1[i];
        float v[4] = {a.x + c.x, a.y + c.y, a.z + c.z, a.w + c.w};
        __half hi[4], lo[4];
#pragma unroll
        for (int e = 0; e < 4; e++) {
            hi[e] = __float2half_rn(v[e]);
            lo[e] = __float2half_rn(v[e] - __half2float(hi[e]));
        }
        uint32_t off = SW128((uint32_t)(i >> 4) * 128 + (uint32_t)(i & 15) * 8);
        *(uint2*)(qsm + off)        = *(uint2*)hi;    // plane 0 (hi)
        *(uint2*)(qsm + 8192 + off) = *(uint2*)lo;    // plane 1 (lo)
    }

    const __half* Qb = g_q + (size_t)b * CH * NPIX + (size_t)h * HD * NPIX;

    // prologue: tile nbase -> buf 0
#pragma unroll
    for (int l = 0; l < 4; l++) {
        int i = tid + l * 256;
        int s = i >> 9, j = i & 511;
        int d = j >> 3, c = j & 7;
        uint32_t off = QB[0] + (uint32_t)s * 8192 + SW128((uint32_t)d * 128 + c * 16);
        CP_ASYNC16(off, Qb + (size_t)d * NPIX + nbase * 128 + s * 64 + c * 8);
    }
    CP_COMMIT();

    const int warp_m = (wid & 1) * 32;                      // d' range
    const int wn = wid >> 1;                                // 0..3, n base = wn*32
    const int r0 = lane >> 2, c0 = (lane & 3) * 2;

#pragma unroll 1
    for (int t = 0; t < 2; t++) {
        const int nt = nbase + t;
        if (t == 0) {
            // prefetch second tile into buf 1
#pragma unroll
            for (int l = 0; l < 4; l++) {
                int i = tid + l * 256;
                int s = i >> 9, j = i & 511;
                int d = j >> 3, c = j & 7;
                uint32_t off = QB[1] + (uint32_t)s * 8192 + SW128((uint32_t)d * 128 + c * 16);
                CP_ASYNC16(off, Qb + (size_t)d * NPIX + (nbase + 1) * 128 + s * 64 + c * 8);
            }
            CP_COMMIT();
            CP_WAIT1();        // tile nbase's group drained
        } else {
            CP_WAIT0();        // tile nbase+1 drained
        }
        __syncthreads();       // publish tile (and Msp planes on first iter)

        const uint32_t qsub = QB[t] + (uint32_t)(wn >> 1) * 8192;
        const uint32_t colb = (uint32_t)(wn & 1) * 64;

        float acc[2][4][4];
#pragma unroll
        for (int mt = 0; mt < 2; mt++)
#pragma unroll
            for (int nn = 0; nn < 4; nn++)
#pragma unroll
                for (int e = 0; e < 4; e++) acc[mt][nn][e] = 0.0f;

#pragma unroll
        for (int plane = 0; plane < 2; plane++) {
            const uint32_t Ab = base + plane * 8192;
#pragma unroll
            for (int s = 0; s < 4; s++) {
                uint32_t af[2][4], bf[2][4];
#pragma unroll
                for (int mt = 0; mt < 2; mt++)
                    ldsm_x4(af[mt][0], af[mt][1], af[mt][2], af[mt][3],
                            Ab + SW128((uint32_t)(warp_m + mt * 16 + (lane & 15)) * 128
                                       + s * 32 + (lane >> 4) * 16));
                const int krow = s * 16 + (lane & 7) + ((lane >> 3) & 1) * 8;
#pragma unroll
                for (int nb = 0; nb < 2; nb++)
                    ldsm_x4_t(bf[nb][0], bf[nb][1], bf[nb][2], bf[nb][3],
                              qsub + SW128((uint32_t)krow * 128 + colb + nb * 32
                                           + (lane >> 4) * 16));
#pragma unroll
                for (int mt = 0; mt < 2; mt++)
#pragma unroll
                    for (int nn = 0; nn < 4; nn++)
                        mma16816(acc[mt][nn], af[mt], &bf[nn >> 1][(nn & 1) * 2]);
            }
        }

        // epilogue: spike(0.25*D) -> ds -> coalesced os_t rows
#pragma unroll
        for (int mt = 0; mt < 2; mt++)
#pragma unroll
            for (int half = 0; half < 2; half++) {
                const int dp = warp_m + mt * 16 + r0 + half * 8;
#pragma unroll
                for (int nn = 0; nn < 4; nn++) {
                    const int nloc = wn * 32 + nn * 8 + c0;
                    float y0 = spikef(acc[mt][nn][half * 2 + 0] * 0.25f);
                    float y1 = spikef(acc[mt][nn][half * 2 + 1] * 0.25f);
                    *reinterpret_cast<__half2*>(ds + dp * 132 + nloc) =
                        __floats2half2_rn(y0, y1);
                }
            }
        __syncthreads();

        if (tid < 128) {
            __half hv[64];
#pragma unroll
            for (int dp = 0; dp < 64; dp++) hv[dp] = ds[dp * 132 + tid];
            __half* Ob = g_os_t + (size_t)b * NPIX * CH
                       + (size_t)(nt * 128 + tid) * CH + h * 64;
#pragma unroll
            for (int i = 0; i < 8; i++)
                *reinterpret_cast<int4*>(Ob + i * 8) = reinterpret_cast<int4*>(hv)[i];
        }
        if (t == 0) __syncthreads();   // ds free before next iter's epilogue writes
    }
}

// ---------------------------------------------------------------------------
// launch
// ---------------------------------------------------------------------------
static constexpr int CONV_SMEM = 3 * 24576 + 1024;   // 74752

extern "C" void kernel_launch(void* const* d_in, const int* in_sizes, int n_in,
                              void* d_out, int out_size) {
    (void)in_sizes; (void)n_in; (void)out_size;
    const float* x  = (const float*)d_in[0];
    const float* qw = (const float*)d_in[1];
    const float* qg = (const float*)d_in[2];
    const float* qb = (const float*)d_in[3];
    const float* qm = (const float*)d_in[4];
    const float* qv = (const float*)d_in[5];
    const float* kw = (const float*)d_in[6];
    const float* kg = (const float*)d_in[7];
    const float* kb = (const float*)d_in[8];
    const float* km = (const float*)d_in[9];
    const float* kv = (const float*)d_in[10];
    const float* vw = (const float*)d_in[11];
    const float* vg = (const float*)d_in[12];
    const float* vb = (const float*)d_in[13];
    const float* vm = (const float*)d_in[14];
    const float* vv = (const float*)d_in[15];
    const float* pw = (const float*)d_in[16];
    const float* pg = (const float*)d_in[17];
    const float* pb = (const float*)d_in[18];
    const float* pm = (const float*)d_in[19];
    const float* pv = (const float*)d_in[20];
    float* out = (float*)d_out;

    __half *xs_t, *q, *k, *v, *os_t, *wsp;
    float *bns, *bnb;
    cudaGetSymbolAddress((void**)&xs_t, g_xs_t);
    cudaGetSymbolAddress((void**)&q,    g_q);
    cudaGetSymbolAddress((void**)&k,    g_k);
    cudaGetSymbolAddress((void**)&v,    g_v);
    cudaGetSymbolAddress((void**)&os_t, g_os_t);
    cudaGetSymbolAddress((void**)&wsp,  g_wsplit);
    cudaGetSymbolAddress((void**)&bns,  g_bns);
    cudaGetSymbolAddress((void**)&bnb,  g_bnb);

    static bool attr_done = false;
    if (!attr_done) {
        cudaFuncSetAttribute(conv_mma_kernel<true,  true,  __half>,
                             cudaFuncAttributeMaxDynamicSharedMemorySize, CONV_SMEM);
        cudaFuncSetAttribute(conv_mma_kernel<false, false, float>,
                             cudaFuncAttributeMaxDynamicSharedMemorySize, CONV_SMEM);
        cudaFuncSetAttribute(qm_tc_kernel,
                             cudaFuncAttributeMaxDynamicSharedMemorySize, QM_SMEM);
        attr_done = true;
    }

    // fused preprocessing: 4096 wsplit + 4096 spike_t + 8 bn_prep blocks
    preproc_kernel<<<8200, 256>>>(x, qw, kw, vw, pw,
                                  qg, qb, qm, qv, kg, kb, km, kv,
                                  vg, vb, vm, vv, pg, pb, pm, pv);

    // fused q,k,v conv: M = 1536, tiles (16 n, 12 m, 8 b)  [R7 best config]
    conv_mma_kernel<true, true, __half><<<dim3(16, 12, 8), 256, CONV_SMEM>>>(
        wsp, xs_t, bns, bnb, q, k, v);

    ktv_mma_kernel<<<dim3(2, 64), 256>>>();
    qm_tc_kernel<<<dim3(4, 64), 256, QM_SMEM>>>();

    const size_t WS = (size_t)512 * 1024;
    conv_mma_kernel<false, false, float><<<dim3(16, 4, 8), 256, CONV_SMEM>>>(
        wsp + 3 * WS, os_t, bns + 3 * CH, bnb + 3 * CH, out, nullptr, nullptr);
}